// round 4
// baseline (speedup 1.0000x reference)
#include <cuda_runtime.h>
#include <math.h>

#define NB 8192
typedef unsigned long long u64;

// ---------------- device scratch ----------------
__device__ float  g_y1[(size_t)NB * 64 * 14 * 14];   // conv1 pre-BN output
__device__ float  g_y2[(size_t)NB * 128 * 7 * 7];    // conv2 pre-BN output
__device__ double g_acc[448];
__device__ float  g_scale[224];
__device__ float  g_shift[224];

// ---------------- f32x2 helpers ----------------
__device__ __forceinline__ void ffma2(u64 &d, u64 a, u64 b) {
    asm("fma.rn.f32x2 %0, %1, %2, %0;" : "+l"(d) : "l"(a), "l"(b));
}
__device__ __forceinline__ void fadd2(u64 &d, u64 a) {
    asm("add.rn.f32x2 %0, %0, %1;" : "+l"(d) : "l"(a));
}
__device__ __forceinline__ u64 pack2(float x, float y) {
    u64 r; asm("mov.b64 %0, {%1, %2};" : "=l"(r) : "f"(x), "f"(y)); return r;
}
__device__ __forceinline__ float2 unpack2(u64 v) {
    float2 r; asm("mov.b64 {%0, %1}, %2;" : "=f"(r.x), "=f"(r.y) : "l"(v)); return r;
}

// ---------------- zero stats ----------------
__global__ void k_zero() {
    int i = blockIdx.x * blockDim.x + threadIdx.x;
    if (i < 448) g_acc[i] = 0.0;
}

// ---------------- stage0 stats: conv0 (+bias), accumulate sum/sumsq ----------------
__global__ void __launch_bounds__(256) k_stats0(const float* __restrict__ x,
                                                const float* __restrict__ w0,
                                                const float* __restrict__ b0) {
    __shared__ float sx[30 * 28];
    __shared__ float sw[288];
    __shared__ float sb[32];
    __shared__ float ssum[32], ssq[32];
    int tid = threadIdx.x;
    int n = blockIdx.x;
    const float* xim = x + (size_t)n * 784;
    for (int i = tid; i < 840; i += 256) {
        int r = i / 28;
        sx[i] = (r >= 1 && r <= 28) ? xim[i - 28] : 0.f;
    }
    for (int i = tid; i < 288; i += 256) sw[i] = w0[i];
    if (tid < 32) { sb[tid] = b0[tid]; ssum[tid] = 0.f; ssq[tid] = 0.f; }
    __syncthreads();

#define LDROW(SR, X0, X1, X2) { const float* _p = &sx[(SR) * 28 + col]; \
        X0 = mL ? _p[-1] : 0.f; X1 = _p[0]; X2 = mR ? _p[1] : 0.f; }

    for (int task = tid; task < 896; task += 256) {
        int c = task / 28, col = task % 28;
        float w[9];
#pragma unroll
        for (int i = 0; i < 9; i++) w[i] = sw[c * 9 + i];
        float bias = sb[c];
        bool mL = col > 0, mR = col < 27;
        float a0, a1, a2, d0, d1, d2, e0, e1, e2;
        LDROW(0, a0, a1, a2);
        LDROW(1, d0, d1, d2);
        float ls = 0.f, lq = 0.f;
        for (int r = 0; r < 28; r++) {
            LDROW(r + 2, e0, e1, e2);
            float acc = bias;
            acc += w[0] * a0 + w[1] * a1 + w[2] * a2;
            acc += w[3] * d0 + w[4] * d1 + w[5] * d2;
            acc += w[6] * e0 + w[7] * e1 + w[8] * e2;
            ls += acc; lq += acc * acc;
            a0 = d0; a1 = d1; a2 = d2;
            d0 = e0; d1 = e1; d2 = e2;
        }
        atomicAdd(&ssum[c], ls);
        atomicAdd(&ssq[c], lq);
    }
    __syncthreads();
    if (tid < 32) {
        atomicAdd(&g_acc[tid], (double)ssum[tid]);
        atomicAdd(&g_acc[32 + tid], (double)ssq[tid]);
    }
}

// ---------------- finalize BN ----------------
__global__ void k_fin(int acc_off, int C, double inv_n,
                      const float* __restrict__ g, const float* __restrict__ be, int so) {
    int c = threadIdx.x;
    if (c < C) {
        double mean = g_acc[acc_off + c] * inv_n;
        double var = g_acc[acc_off + C + c] * inv_n - mean * mean;
        float s = g[c] * rsqrtf((float)var + 1e-5f);
        g_scale[so + c] = s;
        g_shift[so + c] = be[c] - (float)mean * s;
    }
}

// ---------------- fused conv0+bn0+relu -> conv1, store y1, stats1 ----------------
// block = half image, 256 threads, split-K GEMM (2 groups x 112 threads)
// sa layout: [32ci][14r][2 parity][16]  (cols de-interleaved, padded 14->16)
// smem floats: sa 14336 | sw1t 8704 | sx 448 | sw0 288 | sb0 32 | ssum 64 | ssq 64
//   = 23936 floats = 95744 B  (2 blocks / SM)
__global__ void __launch_bounds__(256, 2) k_conv1(const float* __restrict__ x,
                                                  const float* __restrict__ w0,
                                                  const float* __restrict__ b0,
                                                  const float* __restrict__ w1,
                                                  const float* __restrict__ b1) {
    extern __shared__ float sm[];
    float* sa   = sm;            // 14336
    float* sw1t = sm + 14336;    // [128][68]
    float* sx   = sm + 23040;    // [16][28]
    float* sw0  = sm + 23488;    // 288
    float* sb0  = sm + 23776;    // 32
    float* ssum = sm + 23808;    // 64
    float* ssq  = sm + 23872;    // 64

    int tid = threadIdx.x;
    int n = blockIdx.x >> 1;
    int half = blockIdx.x & 1;
    int r0 = half * 14;
    const float* xim = x + (size_t)n * 784;

    for (int i = tid; i < 448; i += 256) {
        int lr = i / 28;
        int gr = r0 - 1 + lr;
        sx[i] = (gr >= 0 && gr < 28) ? xim[gr * 28 + (i % 28)] : 0.f;
    }
    for (int i = tid; i < 288; i += 256) sw0[i] = w0[i];
    if (tid < 32) sb0[tid] = b0[tid];
    if (tid < 64) { ssum[tid] = 0.f; ssq[tid] = 0.f; }
    for (int i = tid; i < 8192; i += 256) {
        int co = i >> 7, kl = i & 127;
        sw1t[kl * 68 + co] = w1[i];
    }
    // zero the pad columns of sa (idx 14,15 of each (c,lr,parity) row)
    for (int i = tid; i < 1792; i += 256) {
        int c = i / 56, rem = i % 56;
        int lr = rem >> 2, p = (rem >> 1) & 1, q = 14 + (rem & 1);
        sa[((c * 14 + lr) * 2 + p) * 16 + q] = 0.f;
    }
    __syncthreads();

#define LDX(SR, X0, X1, X2) { const float* _p = &sx[(SR) * 28 + col]; \
        X0 = mL ? _p[-1] : 0.f; X1 = _p[0]; X2 = mR ? _p[1] : 0.f; }

    // conv0 + bn0 + relu into sa (parity layout)
    for (int task = tid; task < 896; task += 256) {
        int c = task / 28, col = task % 28;
        float w[9];
#pragma unroll
        for (int i = 0; i < 9; i++) w[i] = sw0[c * 9 + i];
        float bias = sb0[c];
        float sc = g_scale[c], sh = g_shift[c];
        bool mL = col > 0, mR = col < 27;
        int pbase = (col & 1) * 16 + (col >> 1);
        float a0, a1, a2, d0, d1, d2, e0, e1, e2;
        LDX(0, a0, a1, a2);
        LDX(1, d0, d1, d2);
#pragma unroll 2
        for (int lr = 0; lr < 14; lr++) {
            LDX(lr + 2, e0, e1, e2);
            float acc = bias;
            acc += w[0] * a0 + w[1] * a1 + w[2] * a2;
            acc += w[3] * d0 + w[4] * d1 + w[5] * d2;
            acc += w[6] * e0 + w[7] * e1 + w[8] * e2;
            float v = fmaf(acc, sc, sh);
            sa[(c * 14 + lr) * 32 + pbase] = fmaxf(v, 0.f);
            a0 = d0; a1 = d1; a2 = d2;
            d0 = e0; d1 = e1; d2 = e2;
        }
    }
    __syncthreads();

    // split-K GEMM: C[64co][7oh x 14ow], per-thread tile 4co x 14ow (as 7 f32x2 pairs)
    int gk = tid >> 7;        // k-group 0/1
    int tt = tid & 127;       // 0..127, active if < 112
    int tco = tt / 7, oh = tt % 7;
    int co0 = tco * 4;
    u64 acc[4][7];
    if (tt < 112) {
#pragma unroll
        for (int j = 0; j < 4; j++) {
            u64 init = 0ull;
            if (gk == 0) { float bb = b1[co0 + j]; init = pack2(bb, bb); }
#pragma unroll
            for (int i = 0; i < 7; i++) acc[j][i] = init;
        }
        int k0 = gk * 64;
#pragma unroll 4
        for (int kk = 0; kk < 64; kk++) {
            int k = k0 + kk;
            const float* ap = &sa[(((k >> 2) * 14 + 2 * oh + ((k >> 1) & 1)) * 2 + (k & 1)) * 16];
            ulonglong2 u0 = ((const ulonglong2*)ap)[0];
            ulonglong2 u1 = ((const ulonglong2*)ap)[1];
            ulonglong2 u2 = ((const ulonglong2*)ap)[2];
            u64 av6 = ((const u64*)ap)[6];
            u64 av[7] = { u0.x, u0.y, u1.x, u1.y, u2.x, u2.y, av6 };
            float4 wv = *(const float4*)&sw1t[k * 68 + co0];
            u64 wj[4] = { pack2(wv.x, wv.x), pack2(wv.y, wv.y),
                          pack2(wv.z, wv.z), pack2(wv.w, wv.w) };
#pragma unroll
            for (int j = 0; j < 4; j++)
#pragma unroll
                for (int i = 0; i < 7; i++)
                    ffma2(acc[j][i], wj[j], av[i]);
        }
    }
    __syncthreads();   // all reads of sa done -> reuse as reduction scratch
    u64* scratch = (u64*)sa;
    if (gk == 1 && tt < 112) {
#pragma unroll
        for (int j = 0; j < 4; j++)
#pragma unroll
            for (int i = 0; i < 7; i++)
                scratch[tt * 28 + j * 7 + i] = acc[j][i];
    }
    __syncthreads();
    if (gk == 0 && tt < 112) {
        int oh_g = half * 7 + oh;
#pragma unroll
        for (int j = 0; j < 4; j++) {
            int co = co0 + j;
            float ls = 0.f, lq = 0.f;
            u64* dst = (u64*)&g_y1[((size_t)(n * 64 + co) * 14 + oh_g) * 14];
#pragma unroll
            for (int i = 0; i < 7; i++) {
                u64 v = acc[j][i];
                fadd2(v, scratch[tt * 28 + j * 7 + i]);
                dst[i] = v;
                float2 f = unpack2(v);
                ls += f.x + f.y;
                lq += f.x * f.x + f.y * f.y;
            }
            atomicAdd(&ssum[co], ls);
            atomicAdd(&ssq[co], lq);
        }
    }
    __syncthreads();
    if (tid < 64) {
        atomicAdd(&g_acc[64 + tid], (double)ssum[tid]);
        atomicAdd(&g_acc[128 + tid], (double)ssq[tid]);
    }
}

// ---------------- fused bn1+relu -> conv2, store y2, stats2 ----------------
// block = 2 images, 448 threads. sa layout: [2img][64ci][14r][2 parity][8]
// smem floats: sa 28672 | swc 16896 | ssum 128 | ssq 128 = 45824 floats = 183296 B
__global__ void __launch_bounds__(448, 1) k_conv2(const float* __restrict__ w2,
                                                  const float* __restrict__ b2) {
    extern __shared__ float sm[];
    float* sa   = sm;            // 28672
    float* swc  = sm + 28672;    // [128][132]
    float* ssum = sm + 45568;    // 128
    float* ssq  = sm + 45696;    // 128
    int tid = threadIdx.x;
    int n0 = blockIdx.x * 2;
    if (tid < 128) { ssum[tid] = 0.f; ssq[tid] = 0.f; }

    // zero pads (q=7, both parities)
    for (int i = tid; i < 3584; i += 448) {
        // i indexes (img,ci,row,parity)
        sa[i * 8 + 7] = 0.f;
    }
    // load y1 with bn1+relu, de-interleave into parity layout
    for (int i = tid; i < 12544; i += 448) {
        int img = i / 6272, r2 = i % 6272;
        int ci = r2 / 98, rem = r2 % 98;
        int row = rem / 7, q = rem % 7;
        float sc = g_scale[32 + ci], sh = g_shift[32 + ci];
        float2 v = ((const float2*)(g_y1 + ((size_t)(n0 + img) * 64 + ci) * 196 + row * 14))[q];
        float e = fmaxf(fmaf(v.x, sc, sh), 0.f);
        float o = fmaxf(fmaf(v.y, sc, sh), 0.f);
        int base = ((img * 64 + ci) * 14 + row) * 16;
        sa[base + q] = e;
        sa[base + 8 + q] = o;
    }

    // GEMM: per image C[128co][7oh x 7ow], per-thread 4co x 8p(7 real) as 4 pairs
    int img = tid / 224, tt = tid % 224;
    int tco = tt / 7, oh = tt % 7;
    int co0 = tco * 4;
    u64 acc[4][4];
#pragma unroll
    for (int j = 0; j < 4; j++) {
        float bb = b2[co0 + j];
        u64 init = pack2(bb, bb);
#pragma unroll
        for (int i = 0; i < 4; i++) acc[j][i] = init;
    }
    const float* saimg = sa + img * 14336;

    for (int kc = 0; kc < 2; kc++) {
        __syncthreads();
        for (int idx = tid; idx < 16384; idx += 448) {
            int co = idx >> 7, kl = idx & 127;
            swc[kl * 132 + co] = w2[co * 256 + kc * 128 + kl];
        }
        __syncthreads();
#pragma unroll 4
        for (int kl = 0; kl < 128; kl++) {
            int k = kc * 128 + kl;
            const float* ap = &saimg[(((k >> 2) * 14 + 2 * oh + ((k >> 1) & 1)) * 2 + (k & 1)) * 8];
            ulonglong2 u0 = ((const ulonglong2*)ap)[0];
            ulonglong2 u1 = ((const ulonglong2*)ap)[1];
            u64 av[4] = { u0.x, u0.y, u1.x, u1.y };
            float4 wv = *(const float4*)&swc[kl * 132 + co0];
            u64 wj[4] = { pack2(wv.x, wv.x), pack2(wv.y, wv.y),
                          pack2(wv.z, wv.z), pack2(wv.w, wv.w) };
#pragma unroll
            for (int j = 0; j < 4; j++)
#pragma unroll
                for (int i = 0; i < 4; i++)
                    ffma2(acc[j][i], wj[j], av[i]);
        }
    }

    int n = n0 + img;
#pragma unroll
    for (int j = 0; j < 4; j++) {
        int co = co0 + j;
        float ls = 0.f, lq = 0.f;
        float* dst = g_y2 + (size_t)(n * 128 + co) * 49 + oh * 7;
#pragma unroll
        for (int i = 0; i < 4; i++) {
            float2 f = unpack2(acc[j][i]);
            dst[2 * i] = f.x;
            ls += f.x; lq += f.x * f.x;
            if (i < 3) {               // skip pad (p=7)
                dst[2 * i + 1] = f.y;
                ls += f.y; lq += f.y * f.y;
            }
        }
        atomicAdd(&ssum[co], ls);
        atomicAdd(&ssq[co], lq);
    }
    __syncthreads();
    if (tid < 128) {
        atomicAdd(&g_acc[192 + tid], (double)ssum[tid]);
        atomicAdd(&g_acc[320 + tid], (double)ssq[tid]);
    }
}

// ---------------- bn2+relu + global avg pool + FC ----------------
__global__ void __launch_bounds__(128) k_head(const float* __restrict__ wfc,
                                              const float* __restrict__ bfc,
                                              float* __restrict__ out) {
    __shared__ float sraw[6272];
    __shared__ float pooled[128];
    int tid = threadIdx.x, n = blockIdx.x;
    const float* y2 = g_y2 + (size_t)n * 6272;
    for (int i = tid; i < 6272; i += 128) sraw[i] = y2[i];
    __syncthreads();
    {
        int c = tid;
        float sc = g_scale[96 + c], sh = g_shift[96 + c];
        float s = 0.f;
        const float* p = &sraw[c * 49];
#pragma unroll
        for (int i = 0; i < 49; i++) s += fmaxf(fmaf(p[i], sc, sh), 0.f);
        pooled[c] = s * (1.f / 49.f);
    }
    __syncthreads();
    if (tid < 10) {
        float o = bfc[tid];
        const float* wr = wfc + tid * 128;
#pragma unroll 8
        for (int c = 0; c < 128; c++) o = fmaf(pooled[c], wr[c], o);
        out[(size_t)n * 10 + tid] = o;
    }
}

// ---------------- launch ----------------
extern "C" void kernel_launch(void* const* d_in, const int* in_sizes, int n_in,
                              void* d_out, int out_size) {
    const float* x   = (const float*)d_in[0];
    const float* w0  = (const float*)d_in[1];
    const float* b0  = (const float*)d_in[2];
    const float* g0  = (const float*)d_in[3];
    const float* be0 = (const float*)d_in[4];
    const float* w1  = (const float*)d_in[5];
    const float* b1  = (const float*)d_in[6];
    const float* g1  = (const float*)d_in[7];
    const float* be1 = (const float*)d_in[8];
    const float* w2  = (const float*)d_in[9];
    const float* b2  = (const float*)d_in[10];
    const float* g2  = (const float*)d_in[11];
    const float* be2 = (const float*)d_in[12];
    const float* wfc = (const float*)d_in[13];
    const float* bfc = (const float*)d_in[14];
    float* out = (float*)d_out;

    cudaFuncSetAttribute(k_conv1, cudaFuncAttributeMaxDynamicSharedMemorySize, 95744);
    cudaFuncSetAttribute(k_conv2, cudaFuncAttributeMaxDynamicSharedMemorySize, 183296);

    k_zero<<<2, 256>>>();
    k_stats0<<<NB, 256>>>(x, w0, b0);
    k_fin<<<1, 128>>>(0, 32, 1.0 / (8192.0 * 784.0), g0, be0, 0);
    k_conv1<<<NB * 2, 256, 95744>>>(x, w0, b0, w1, b1);
    k_fin<<<1, 128>>>(64, 64, 1.0 / (8192.0 * 196.0), g1, be1, 32);
    k_conv2<<<NB / 2, 448, 183296>>>(w2, b2);
    k_fin<<<1, 128>>>(192, 128, 1.0 / (8192.0 * 49.0), g2, be2, 96);
    k_head<<<NB, 128>>>(wfc, bfc, out);
}

// round 5
// speedup vs baseline: 2.5371x; 2.5371x over previous
#include <cuda_runtime.h>
#include <math.h>

#define NB 8192
typedef unsigned long long u64;

// ---------------- device scratch ----------------
__device__ float  g_y1[(size_t)NB * 64 * 14 * 14];   // conv1 pre-BN output
__device__ float  g_y2[(size_t)NB * 128 * 7 * 7];    // conv2 pre-BN output
__device__ double g_acc[448];
__device__ float  g_scale[224];
__device__ float  g_shift[224];

// ---------------- f32x2 helpers ----------------
__device__ __forceinline__ void ffma2(u64 &d, u64 a, u64 b) {
    asm("fma.rn.f32x2 %0, %1, %2, %0;" : "+l"(d) : "l"(a), "l"(b));
}
__device__ __forceinline__ void fadd2(u64 &d, u64 a) {
    asm("add.rn.f32x2 %0, %0, %1;" : "+l"(d) : "l"(a));
}
__device__ __forceinline__ u64 pack2(float x, float y) {
    u64 r; asm("mov.b64 %0, {%1, %2};" : "=l"(r) : "f"(x), "f"(y)); return r;
}
__device__ __forceinline__ float2 unpack2(u64 v) {
    float2 r; asm("mov.b64 {%0, %1}, %2;" : "=f"(r.x), "=f"(r.y) : "l"(v)); return r;
}

// ---------------- zero stats ----------------
__global__ void k_zero() {
    int i = blockIdx.x * blockDim.x + threadIdx.x;
    if (i < 448) g_acc[i] = 0.0;
}

// ---------------- stage0 stats: conv0 (+bias), accumulate sum/sumsq ----------------
__global__ void __launch_bounds__(256) k_stats0(const float* __restrict__ x,
                                                const float* __restrict__ w0,
                                                const float* __restrict__ b0) {
    __shared__ float sx[30 * 28];
    __shared__ float sw[288];
    __shared__ float sb[32];
    __shared__ float ssum[32], ssq[32];
    int tid = threadIdx.x;
    int n = blockIdx.x;
    const float* xim = x + (size_t)n * 784;
    for (int i = tid; i < 840; i += 256) {
        int r = i / 28;
        sx[i] = (r >= 1 && r <= 28) ? xim[i - 28] : 0.f;
    }
    for (int i = tid; i < 288; i += 256) sw[i] = w0[i];
    if (tid < 32) { sb[tid] = b0[tid]; ssum[tid] = 0.f; ssq[tid] = 0.f; }
    __syncthreads();

#define LDROW(SR, X0, X1, X2) { const float* _p = &sx[(SR) * 28 + col]; \
        X0 = mL ? _p[-1] : 0.f; X1 = _p[0]; X2 = mR ? _p[1] : 0.f; }

    for (int task = tid; task < 896; task += 256) {
        int c = task / 28, col = task % 28;
        float w[9];
#pragma unroll
        for (int i = 0; i < 9; i++) w[i] = sw[c * 9 + i];
        float bias = sb[c];
        bool mL = col > 0, mR = col < 27;
        float a0, a1, a2, d0, d1, d2, e0, e1, e2;
        LDROW(0, a0, a1, a2);
        LDROW(1, d0, d1, d2);
        float ls = 0.f, lq = 0.f;
        for (int r = 0; r < 28; r++) {
            LDROW(r + 2, e0, e1, e2);
            float acc = bias;
            acc += w[0] * a0 + w[1] * a1 + w[2] * a2;
            acc += w[3] * d0 + w[4] * d1 + w[5] * d2;
            acc += w[6] * e0 + w[7] * e1 + w[8] * e2;
            ls += acc; lq += acc * acc;
            a0 = d0; a1 = d1; a2 = d2;
            d0 = e0; d1 = e1; d2 = e2;
        }
        atomicAdd(&ssum[c], ls);
        atomicAdd(&ssq[c], lq);
    }
    __syncthreads();
    if (tid < 32) {
        atomicAdd(&g_acc[tid], (double)ssum[tid]);
        atomicAdd(&g_acc[32 + tid], (double)ssq[tid]);
    }
}

// ---------------- finalize BN ----------------
__global__ void k_fin(int acc_off, int C, double inv_n,
                      const float* __restrict__ g, const float* __restrict__ be, int so) {
    int c = threadIdx.x;
    if (c < C) {
        double mean = g_acc[acc_off + c] * inv_n;
        double var = g_acc[acc_off + C + c] * inv_n - mean * mean;
        float s = g[c] * rsqrtf((float)var + 1e-5f);
        g_scale[so + c] = s;
        g_shift[so + c] = be[c] - (float)mean * s;
    }
}

// ---------------- fused conv0+bn0+relu -> conv1, store y1, stats1 ----------------
// block = half image, 256 threads, split-K GEMM (2 groups x 112 threads)
// sa layout: [32ci][14r]{[2 parity][16] + 4 pad} -> row stride 36 floats (144B)
//   144B stride => the 2 oh values per warp land in different banks (no conflicts)
// lane map: tco = tt&15 (fast), oh = tt>>4 -> activation loads broadcast
// smem floats: sa 16128 | sw1t 8704 | sx 448 | sw0 288 | sb0 32 | ssum 64 | ssq 64
//   = 25728 floats = 102912 B (2 blocks / SM)
__global__ void __launch_bounds__(256, 2) k_conv1(const float* __restrict__ x,
                                                  const float* __restrict__ w0,
                                                  const float* __restrict__ b0,
                                                  const float* __restrict__ w1,
                                                  const float* __restrict__ b1) {
    extern __shared__ float sm[];
    float* sa   = sm;            // 16128
    float* sw1t = sm + 16128;    // [128][68]
    float* sx   = sm + 24832;    // [16][28]
    float* sw0  = sm + 25280;    // 288
    float* sb0  = sm + 25568;    // 32
    float* ssum = sm + 25600;    // 64
    float* ssq  = sm + 25664;    // 64

    int tid = threadIdx.x;
    int n = blockIdx.x >> 1;
    int half = blockIdx.x & 1;
    int r0 = half * 14;
    const float* xim = x + (size_t)n * 784;

    for (int i = tid; i < 448; i += 256) {
        int lr = i / 28;
        int gr = r0 - 1 + lr;
        sx[i] = (gr >= 0 && gr < 28) ? xim[gr * 28 + (i % 28)] : 0.f;
    }
    for (int i = tid; i < 288; i += 256) sw0[i] = w0[i];
    if (tid < 32) sb0[tid] = b0[tid];
    if (tid < 64) { ssum[tid] = 0.f; ssq[tid] = 0.f; }
    for (int i = tid; i < 8192; i += 256) {
        int co = i >> 7, kl = i & 127;
        sw1t[kl * 68 + co] = w1[i];
    }
    __syncthreads();

#define LDX(SR, X0, X1, X2) { const float* _p = &sx[(SR) * 28 + col]; \
        X0 = mL ? _p[-1] : 0.f; X1 = _p[0]; X2 = mR ? _p[1] : 0.f; }

    // conv0 + bn0 + relu into sa (parity layout, 144B row stride)
    for (int task = tid; task < 896; task += 256) {
        int c = task / 28, col = task % 28;
        float w[9];
#pragma unroll
        for (int i = 0; i < 9; i++) w[i] = sw0[c * 9 + i];
        float bias = sb0[c];
        float sc = g_scale[c], sh = g_shift[c];
        bool mL = col > 0, mR = col < 27;
        int pbase = (col & 1) * 16 + (col >> 1);
        float a0, a1, a2, d0, d1, d2, e0, e1, e2;
        LDX(0, a0, a1, a2);
        LDX(1, d0, d1, d2);
#pragma unroll 2
        for (int lr = 0; lr < 14; lr++) {
            LDX(lr + 2, e0, e1, e2);
            float acc = bias;
            acc += w[0] * a0 + w[1] * a1 + w[2] * a2;
            acc += w[3] * d0 + w[4] * d1 + w[5] * d2;
            acc += w[6] * e0 + w[7] * e1 + w[8] * e2;
            float v = fmaf(acc, sc, sh);
            sa[(c * 14 + lr) * 36 + pbase] = fmaxf(v, 0.f);
            a0 = d0; a1 = d1; a2 = d2;
            d0 = e0; d1 = e1; d2 = e2;
        }
    }
    __syncthreads();

    // split-K GEMM: C[64co][7oh x 14ow], per-thread tile 4co x 14ow (7 f32x2 pairs)
    int gk = tid >> 7;        // k-group 0/1
    int tt = tid & 127;       // 0..127, active if < 112
    int tco = tt & 15;        // FAST lane index -> weight loads spread, acts broadcast
    int oh = tt >> 4;         // 0..7 (7 => inactive)
    int co0 = tco * 4;
    u64 acc[4][7];
    if (tt < 112) {
#pragma unroll
        for (int j = 0; j < 4; j++) {
            u64 init = 0ull;
            if (gk == 0) { float bb = b1[co0 + j]; init = pack2(bb, bb); }
#pragma unroll
            for (int i = 0; i < 7; i++) acc[j][i] = init;
        }
        int k0 = gk * 64;
#pragma unroll 4
        for (int kk = 0; kk < 64; kk++) {
            int k = k0 + kk;
            const float* ap = &sa[((k >> 2) * 14 + 2 * oh + ((k >> 1) & 1)) * 36 + (k & 1) * 16];
            ulonglong2 u0 = ((const ulonglong2*)ap)[0];
            ulonglong2 u1 = ((const ulonglong2*)ap)[1];
            ulonglong2 u2 = ((const ulonglong2*)ap)[2];
            u64 av6 = ((const u64*)ap)[6];
            u64 av[7] = { u0.x, u0.y, u1.x, u1.y, u2.x, u2.y, av6 };
            float4 wv = *(const float4*)&sw1t[k * 68 + co0];
            u64 wj[4] = { pack2(wv.x, wv.x), pack2(wv.y, wv.y),
                          pack2(wv.z, wv.z), pack2(wv.w, wv.w) };
#pragma unroll
            for (int j = 0; j < 4; j++)
#pragma unroll
                for (int i = 0; i < 7; i++)
                    ffma2(acc[j][i], wj[j], av[i]);
        }
    }
    __syncthreads();   // all reads of sa done -> reuse as reduction scratch
    u64* scratch = (u64*)sa;
    if (gk == 1 && tt < 112) {
#pragma unroll
        for (int j = 0; j < 4; j++)
#pragma unroll
            for (int i = 0; i < 7; i++)
                scratch[tt * 28 + j * 7 + i] = acc[j][i];
    }
    __syncthreads();
    if (gk == 0 && tt < 112) {
        int oh_g = half * 7 + oh;
#pragma unroll
        for (int j = 0; j < 4; j++) {
            int co = co0 + j;
            float ls = 0.f, lq = 0.f;
            u64* dst = (u64*)&g_y1[((size_t)(n * 64 + co) * 14 + oh_g) * 14];
#pragma unroll
            for (int i = 0; i < 7; i++) {
                u64 v = acc[j][i];
                fadd2(v, scratch[tt * 28 + j * 7 + i]);
                dst[i] = v;
                float2 f = unpack2(v);
                ls += f.x + f.y;
                lq += f.x * f.x + f.y * f.y;
            }
            atomicAdd(&ssum[co], ls);
            atomicAdd(&ssq[co], lq);
        }
    }
    __syncthreads();
    if (tid < 64) {
        atomicAdd(&g_acc[64 + tid], (double)ssum[tid]);
        atomicAdd(&g_acc[128 + tid], (double)ssq[tid]);
    }
}

// ---------------- fused bn1+relu -> conv2, store y2, stats2 ----------------
// block = 2 images, 448 threads. sa layout: [2img][64ci][14r][2 parity][8]
// lane map: tco = tt&31 (fast), oh = tt/32 -> activation loads fully broadcast
// smem floats: sa 28672 | swc 16896 | ssum 128 | ssq 128 = 45824 floats = 183296 B
__global__ void __launch_bounds__(448, 1) k_conv2(const float* __restrict__ w2,
                                                  const float* __restrict__ b2) {
    extern __shared__ float sm[];
    float* sa   = sm;            // 28672
    float* swc  = sm + 28672;    // [128][132]
    float* ssum = sm + 45568;    // 128
    float* ssq  = sm + 45696;    // 128
    int tid = threadIdx.x;
    int n0 = blockIdx.x * 2;
    if (tid < 128) { ssum[tid] = 0.f; ssq[tid] = 0.f; }

    // zero pads (q=7, both parities)
    for (int i = tid; i < 3584; i += 448) {
        sa[i * 8 + 7] = 0.f;
    }
    // load y1 with bn1+relu, de-interleave into parity layout
    for (int i = tid; i < 12544; i += 448) {
        int img = i / 6272, r2 = i % 6272;
        int ci = r2 / 98, rem = r2 % 98;
        int row = rem / 7, q = rem % 7;
        float sc = g_scale[32 + ci], sh = g_shift[32 + ci];
        float2 v = ((const float2*)(g_y1 + ((size_t)(n0 + img) * 64 + ci) * 196 + row * 14))[q];
        float e = fmaxf(fmaf(v.x, sc, sh), 0.f);
        float o = fmaxf(fmaf(v.y, sc, sh), 0.f);
        int base = ((img * 64 + ci) * 14 + row) * 16;
        sa[base + q] = e;
        sa[base + 8 + q] = o;
    }

    // GEMM: per image C[128co][7oh x 7ow], per-thread 4co x 8p(7 real) as 4 pairs
    int img = tid / 224, tt = tid % 224;
    int tco = tt & 31;           // FAST lane index
    int oh = tt >> 5;            // 0..6, one oh per warp -> broadcast act loads
    int co0 = tco * 4;
    u64 acc[4][4];
#pragma unroll
    for (int j = 0; j < 4; j++) {
        float bb = b2[co0 + j];
        u64 init = pack2(bb, bb);
#pragma unroll
        for (int i = 0; i < 4; i++) acc[j][i] = init;
    }
    const float* saimg = sa + img * 14336;

    for (int kc = 0; kc < 2; kc++) {
        __syncthreads();
        for (int idx = tid; idx < 16384; idx += 448) {
            int co = idx >> 7, kl = idx & 127;
            swc[kl * 132 + co] = w2[co * 256 + kc * 128 + kl];
        }
        __syncthreads();
#pragma unroll 4
        for (int kl = 0; kl < 128; kl++) {
            int k = kc * 128 + kl;
            const float* ap = &saimg[(((k >> 2) * 14 + 2 * oh + ((k >> 1) & 1)) * 2 + (k & 1)) * 8];
            ulonglong2 u0 = ((const ulonglong2*)ap)[0];
            ulonglong2 u1 = ((const ulonglong2*)ap)[1];
            u64 av[4] = { u0.x, u0.y, u1.x, u1.y };
            float4 wv = *(const float4*)&swc[kl * 132 + co0];
            u64 wj[4] = { pack2(wv.x, wv.x), pack2(wv.y, wv.y),
                          pack2(wv.z, wv.z), pack2(wv.w, wv.w) };
#pragma unroll
            for (int j = 0; j < 4; j++)
#pragma unroll
                for (int i = 0; i < 4; i++)
                    ffma2(acc[j][i], wj[j], av[i]);
        }
    }

    int n = n0 + img;
#pragma unroll
    for (int j = 0; j < 4; j++) {
        int co = co0 + j;
        float ls = 0.f, lq = 0.f;
        float* dst = g_y2 + (size_t)(n * 128 + co) * 49 + oh * 7;
#pragma unroll
        for (int i = 0; i < 4; i++) {
            float2 f = unpack2(acc[j][i]);
            dst[2 * i] = f.x;
            ls += f.x; lq += f.x * f.x;
            if (i < 3) {               // skip pad (p=7)
                dst[2 * i + 1] = f.y;
                ls += f.y; lq += f.y * f.y;
            }
        }
        atomicAdd(&ssum[co], ls);
        atomicAdd(&ssq[co], lq);
    }
    __syncthreads();
    if (tid < 128) {
        atomicAdd(&g_acc[192 + tid], (double)ssum[tid]);
        atomicAdd(&g_acc[320 + tid], (double)ssq[tid]);
    }
}

// ---------------- bn2+relu + global avg pool + FC ----------------
__global__ void __launch_bounds__(128) k_head(const float* __restrict__ wfc,
                                              const float* __restrict__ bfc,
                                              float* __restrict__ out) {
    __shared__ float sraw[6272];
    __shared__ float pooled[128];
    int tid = threadIdx.x, n = blockIdx.x;
    const float* y2 = g_y2 + (size_t)n * 6272;
    for (int i = tid; i < 6272; i += 128) sraw[i] = y2[i];
    __syncthreads();
    {
        int c = tid;
        float sc = g_scale[96 + c], sh = g_shift[96 + c];
        float s = 0.f;
        const float* p = &sraw[c * 49];
#pragma unroll
        for (int i = 0; i < 49; i++) s += fmaxf(fmaf(p[i], sc, sh), 0.f);
        pooled[c] = s * (1.f / 49.f);
    }
    __syncthreads();
    if (tid < 10) {
        float o = bfc[tid];
        const float* wr = wfc + tid * 128;
#pragma unroll 8
        for (int c = 0; c < 128; c++) o = fmaf(pooled[c], wr[c], o);
        out[(size_t)n * 10 + tid] = o;
    }
}

// ---------------- launch ----------------
extern "C" void kernel_launch(void* const* d_in, const int* in_sizes, int n_in,
                              void* d_out, int out_size) {
    const float* x   = (const float*)d_in[0];
    const float* w0  = (const float*)d_in[1];
    const float* b0  = (const float*)d_in[2];
    const float* g0  = (const float*)d_in[3];
    const float* be0 = (const float*)d_in[4];
    const float* w1  = (const float*)d_in[5];
    const float* b1  = (const float*)d_in[6];
    const float* g1  = (const float*)d_in[7];
    const float* be1 = (const float*)d_in[8];
    const float* w2  = (const float*)d_in[9];
    const float* b2  = (const float*)d_in[10];
    const float* g2  = (const float*)d_in[11];
    const float* be2 = (const float*)d_in[12];
    const float* wfc = (const float*)d_in[13];
    const float* bfc = (const float*)d_in[14];
    float* out = (float*)d_out;

    cudaFuncSetAttribute(k_conv1, cudaFuncAttributeMaxDynamicSharedMemorySize, 102912);
    cudaFuncSetAttribute(k_conv2, cudaFuncAttributeMaxDynamicSharedMemorySize, 183296);

    k_zero<<<2, 256>>>();
    k_stats0<<<NB, 256>>>(x, w0, b0);
    k_fin<<<1, 128>>>(0, 32, 1.0 / (8192.0 * 784.0), g0, be0, 0);
    k_conv1<<<NB * 2, 256, 102912>>>(x, w0, b0, w1, b1);
    k_fin<<<1, 128>>>(64, 64, 1.0 / (8192.0 * 196.0), g1, be1, 32);
    k_conv2<<<NB / 2, 448, 183296>>>(w2, b2);
    k_fin<<<1, 128>>>(192, 128, 1.0 / (8192.0 * 49.0), g2, be2, 96);
    k_head<<<NB, 128>>>(wfc, bfc, out);
}

// round 7
// speedup vs baseline: 2.5681x; 1.0122x over previous
#include <cuda_runtime.h>
#include <math.h>

#define NB 8192
typedef unsigned long long u64;

// ---------------- device scratch ----------------
__device__ float  g_y1[(size_t)NB * 64 * 14 * 14];   // conv1 pre-BN output
__device__ float  g_y2[(size_t)NB * 128 * 7 * 7];    // conv2 pre-BN output
__device__ double g_acc[448];
__device__ float  g_scale[224];
__device__ float  g_shift[224];

// ---------------- f32x2 helpers ----------------
__device__ __forceinline__ void ffma2(u64 &d, u64 a, u64 b) {
    asm("fma.rn.f32x2 %0, %1, %2, %0;" : "+l"(d) : "l"(a), "l"(b));
}
__device__ __forceinline__ void fadd2(u64 &d, u64 a) {
    asm("add.rn.f32x2 %0, %0, %1;" : "+l"(d) : "l"(a));
}
__device__ __forceinline__ u64 pack2(float x, float y) {
    u64 r; asm("mov.b64 %0, {%1, %2};" : "=l"(r) : "f"(x), "f"(y)); return r;
}
__device__ __forceinline__ float2 unpack2(u64 v) {
    float2 r; asm("mov.b64 {%0, %1}, %2;" : "=f"(r.x), "=f"(r.y) : "l"(v)); return r;
}

// ---------------- zero stats ----------------
__global__ void k_zero() {
    int i = blockIdx.x * blockDim.x + threadIdx.x;
    if (i < 448) g_acc[i] = 0.0;
}

// ---------------- stage0 stats: conv0 (+bias), accumulate sum/sumsq ----------------
__global__ void __launch_bounds__(256) k_stats0(const float* __restrict__ x,
                                                const float* __restrict__ w0,
                                                const float* __restrict__ b0) {
    __shared__ float sx[30 * 28];
    __shared__ float sw[288];
    __shared__ float sb[32];
    __shared__ float ssum[32], ssq[32];
    int tid = threadIdx.x;
    int n = blockIdx.x;
    const float* xim = x + (size_t)n * 784;
    for (int i = tid; i < 840; i += 256) {
        int r = i / 28;
        sx[i] = (r >= 1 && r <= 28) ? xim[i - 28] : 0.f;
    }
    for (int i = tid; i < 288; i += 256) sw[i] = w0[i];
    if (tid < 32) { sb[tid] = b0[tid]; ssum[tid] = 0.f; ssq[tid] = 0.f; }
    __syncthreads();

#define LDROW(SR, X0, X1, X2) { const float* _p = &sx[(SR) * 28 + col]; \
        X0 = mL ? _p[-1] : 0.f; X1 = _p[0]; X2 = mR ? _p[1] : 0.f; }

    for (int task = tid; task < 896; task += 256) {
        int c = task / 28, col = task % 28;
        float w[9];
#pragma unroll
        for (int i = 0; i < 9; i++) w[i] = sw[c * 9 + i];
        float bias = sb[c];
        bool mL = col > 0, mR = col < 27;
        float a0, a1, a2, d0, d1, d2, e0, e1, e2;
        LDROW(0, a0, a1, a2);
        LDROW(1, d0, d1, d2);
        float ls = 0.f, lq = 0.f;
        for (int r = 0; r < 28; r++) {
            LDROW(r + 2, e0, e1, e2);
            float acc = bias;
            acc += w[0] * a0 + w[1] * a1 + w[2] * a2;
            acc += w[3] * d0 + w[4] * d1 + w[5] * d2;
            acc += w[6] * e0 + w[7] * e1 + w[8] * e2;
            ls += acc; lq += acc * acc;
            a0 = d0; a1 = d1; a2 = d2;
            d0 = e0; d1 = e1; d2 = e2;
        }
        atomicAdd(&ssum[c], ls);
        atomicAdd(&ssq[c], lq);
    }
    __syncthreads();
    if (tid < 32) {
        atomicAdd(&g_acc[tid], (double)ssum[tid]);
        atomicAdd(&g_acc[32 + tid], (double)ssq[tid]);
    }
}

// ---------------- finalize BN ----------------
__global__ void k_fin(int acc_off, int C, double inv_n,
                      const float* __restrict__ g, const float* __restrict__ be, int so) {
    int c = threadIdx.x;
    if (c < C) {
        double mean = g_acc[acc_off + c] * inv_n;
        double var = g_acc[acc_off + C + c] * inv_n - mean * mean;
        float s = g[c] * rsqrtf((float)var + 1e-5f);
        g_scale[so + c] = s;
        g_shift[so + c] = be[c] - (float)mean * s;
    }
}

// ---------------- fused conv0+bn0+relu -> conv1, store y1, stats1 ----------------
// block = half image, 256 threads, split-K GEMM (2 groups x 112 threads)
// sa layout: [32ci][14r]{[2 parity][16] + 4 pad} -> row stride 36 floats (144B)
// lane map: tco = tt&15 (fast), oh = tt>>4 -> activation loads broadcast
__global__ void __launch_bounds__(256, 2) k_conv1(const float* __restrict__ x,
                                                  const float* __restrict__ w0,
                                                  const float* __restrict__ b0,
                                                  const float* __restrict__ w1,
                                                  const float* __restrict__ b1) {
    extern __shared__ float sm[];
    float* sa   = sm;            // 16128
    float* sw1t = sm + 16128;    // [128][68]
    float* sx   = sm + 24832;    // [16][28]
    float* sw0  = sm + 25280;    // 288
    float* sb0  = sm + 25568;    // 32
    float* ssum = sm + 25600;    // 64
    float* ssq  = sm + 25664;    // 64

    int tid = threadIdx.x;
    int n = blockIdx.x >> 1;
    int half = blockIdx.x & 1;
    int r0 = half * 14;
    const float* xim = x + (size_t)n * 784;

    for (int i = tid; i < 448; i += 256) {
        int lr = i / 28;
        int gr = r0 - 1 + lr;
        sx[i] = (gr >= 0 && gr < 28) ? xim[gr * 28 + (i % 28)] : 0.f;
    }
    for (int i = tid; i < 288; i += 256) sw0[i] = w0[i];
    if (tid < 32) sb0[tid] = b0[tid];
    if (tid < 64) { ssum[tid] = 0.f; ssq[tid] = 0.f; }
    for (int i = tid; i < 8192; i += 256) {
        int co = i >> 7, kl = i & 127;
        sw1t[kl * 68 + co] = w1[i];
    }
    __syncthreads();

#define LDX(SR, X0, X1, X2) { const float* _p = &sx[(SR) * 28 + col]; \
        X0 = mL ? _p[-1] : 0.f; X1 = _p[0]; X2 = mR ? _p[1] : 0.f; }

    // conv0 + bn0 + relu into sa (parity layout, 144B row stride)
    for (int task = tid; task < 896; task += 256) {
        int c = task / 28, col = task % 28;
        float w[9];
#pragma unroll
        for (int i = 0; i < 9; i++) w[i] = sw0[c * 9 + i];
        float bias = sb0[c];
        float sc = g_scale[c], sh = g_shift[c];
        bool mL = col > 0, mR = col < 27;
        int pbase = (col & 1) * 16 + (col >> 1);
        float a0, a1, a2, d0, d1, d2, e0, e1, e2;
        LDX(0, a0, a1, a2);
        LDX(1, d0, d1, d2);
#pragma unroll 2
        for (int lr = 0; lr < 14; lr++) {
            LDX(lr + 2, e0, e1, e2);
            float acc = bias;
            acc += w[0] * a0 + w[1] * a1 + w[2] * a2;
            acc += w[3] * d0 + w[4] * d1 + w[5] * d2;
            acc += w[6] * e0 + w[7] * e1 + w[8] * e2;
            float v = fmaf(acc, sc, sh);
            sa[(c * 14 + lr) * 36 + pbase] = fmaxf(v, 0.f);
            a0 = d0; a1 = d1; a2 = d2;
            d0 = e0; d1 = e1; d2 = e2;
        }
    }
    __syncthreads();

    // split-K GEMM, ci-outer / (dy,dx)-unrolled: all LDS get immediate offsets
    int gk = tid >> 7;        // k-group 0/1
    int tt = tid & 127;       // 0..127, active if < 112
    int tco = tt & 15;        // FAST lane index
    int oh = tt >> 4;         // 0..7 (7 => inactive)
    int co0 = tco * 4;
    u64 acc[4][7];
    if (tt < 112) {
#pragma unroll
        for (int j = 0; j < 4; j++) {
            u64 init = 0ull;
            if (gk == 0) { float bb = b1[co0 + j]; init = pack2(bb, bb); }
#pragma unroll
            for (int i = 0; i < 7; i++) acc[j][i] = init;
        }
        int ci0 = gk * 16;
        const float* wp = &sw1t[(ci0 * 4) * 68 + co0];
        const float* ab = &sa[(ci0 * 14 + 2 * oh) * 36];
#pragma unroll 2
        for (int ci = 0; ci < 16; ci++) {
#pragma unroll
            for (int dy = 0; dy < 2; dy++) {
#pragma unroll
                for (int dx = 0; dx < 2; dx++) {
                    const float* ap = ab + dy * 36 + dx * 16;
                    ulonglong2 u0 = ((const ulonglong2*)ap)[0];
                    ulonglong2 u1 = ((const ulonglong2*)ap)[1];
                    ulonglong2 u2 = ((const ulonglong2*)ap)[2];
                    u64 av6 = ((const u64*)ap)[6];
                    u64 av[7] = { u0.x, u0.y, u1.x, u1.y, u2.x, u2.y, av6 };
                    float4 wv = *(const float4*)(wp + (dy * 2 + dx) * 68);
                    u64 wj[4] = { pack2(wv.x, wv.x), pack2(wv.y, wv.y),
                                  pack2(wv.z, wv.z), pack2(wv.w, wv.w) };
#pragma unroll
                    for (int j = 0; j < 4; j++)
#pragma unroll
                        for (int i = 0; i < 7; i++)
                            ffma2(acc[j][i], wj[j], av[i]);
                }
            }
            ab += 14 * 36;
            wp += 4 * 68;
        }
    }
    __syncthreads();   // all reads of sa done -> reuse as reduction scratch
    u64* scratch = (u64*)sa;
    if (gk == 1 && tt < 112) {
#pragma unroll
        for (int j = 0; j < 4; j++)
#pragma unroll
            for (int i = 0; i < 7; i++)
                scratch[tt * 28 + j * 7 + i] = acc[j][i];
    }
    __syncthreads();
    if (gk == 0 && tt < 112) {
        int oh_g = half * 7 + oh;
#pragma unroll
        for (int j = 0; j < 4; j++) {
            int co = co0 + j;
            float ls = 0.f, lq = 0.f;
            u64* dst = (u64*)&g_y1[((size_t)(n * 64 + co) * 14 + oh_g) * 14];
#pragma unroll
            for (int i = 0; i < 7; i++) {
                u64 v = acc[j][i];
                fadd2(v, scratch[tt * 28 + j * 7 + i]);
                dst[i] = v;
                float2 f = unpack2(v);
                ls += f.x + f.y;
                lq += f.x * f.x + f.y * f.y;
            }
            atomicAdd(&ssum[co], ls);
            atomicAdd(&ssq[co], lq);
        }
    }
    __syncthreads();
    if (tid < 64) {
        atomicAdd(&g_acc[64 + tid], (double)ssum[tid]);
        atomicAdd(&g_acc[128 + tid], (double)ssq[tid]);
    }
}

// ---------------- fused bn1+relu -> conv2, store y2, stats2 ----------------
// block = 2 images, 448 threads. sa layout: [2img][64ci][14r][2 parity][8]
// row stride = 16 floats; dy offset = 16, dx (parity) offset = 8
__global__ void __launch_bounds__(448, 1) k_conv2(const float* __restrict__ w2,
                                                  const float* __restrict__ b2) {
    extern __shared__ float sm[];
    float* sa   = sm;            // 28672
    float* swc  = sm + 28672;    // [128][132]
    float* ssum = sm + 45568;    // 128
    float* ssq  = sm + 45696;    // 128
    int tid = threadIdx.x;
    int n0 = blockIdx.x * 2;
    if (tid < 128) { ssum[tid] = 0.f; ssq[tid] = 0.f; }

    // zero pads (q=7, both parities)
    for (int i = tid; i < 3584; i += 448) {
        sa[i * 8 + 7] = 0.f;
    }
    // load y1 with bn1+relu, de-interleave into parity layout
    for (int i = tid; i < 12544; i += 448) {
        int img = i / 6272, r2 = i % 6272;
        int ci = r2 / 98, rem = r2 % 98;
        int row = rem / 7, q = rem % 7;
        float sc = g_scale[32 + ci], sh = g_shift[32 + ci];
        float2 v = ((const float2*)(g_y1 + ((size_t)(n0 + img) * 64 + ci) * 196 + row * 14))[q];
        float e = fmaxf(fmaf(v.x, sc, sh), 0.f);
        float o = fmaxf(fmaf(v.y, sc, sh), 0.f);
        int base = ((img * 64 + ci) * 14 + row) * 16;
        sa[base + q] = e;
        sa[base + 8 + q] = o;
    }

    // GEMM: per image C[128co][7oh x 7ow], per-thread 4co x 8p(7 real) as 4 pairs
    int img = tid / 224, tt = tid % 224;
    int tco = tt & 31;           // FAST lane index
    int oh = tt >> 5;            // 0..6, one oh per warp -> broadcast act loads
    int co0 = tco * 4;
    u64 acc[4][4];
#pragma unroll
    for (int j = 0; j < 4; j++) {
        float bb = b2[co0 + j];
        u64 init = pack2(bb, bb);
#pragma unroll
        for (int i = 0; i < 4; i++) acc[j][i] = init;
    }
    const float* saimg = sa + img * 14336;

    for (int kc = 0; kc < 2; kc++) {
        __syncthreads();
        for (int idx = tid; idx < 16384; idx += 448) {
            int co = idx >> 7, kl = idx & 127;
            swc[kl * 132 + co] = w2[co * 256 + kc * 128 + kl];
        }
        __syncthreads();
        const float* ab = &saimg[(kc * 32 * 14 + 2 * oh) * 16];
        const float* wp = &swc[co0];
#pragma unroll 2
        for (int ci = 0; ci < 32; ci++) {
#pragma unroll
            for (int dy = 0; dy < 2; dy++) {
#pragma unroll
                for (int dx = 0; dx < 2; dx++) {
                    const float* ap = ab + dy * 16 + dx * 8;   // FIX: dy*16 (row stride), was dy*32
                    ulonglong2 u0 = ((const ulonglong2*)ap)[0];
                    ulonglong2 u1 = ((const ulonglong2*)ap)[1];
                    u64 av[4] = { u0.x, u0.y, u1.x, u1.y };
                    float4 wv = *(const float4*)(wp + (dy * 2 + dx) * 132);
                    u64 wj[4] = { pack2(wv.x, wv.x), pack2(wv.y, wv.y),
                                  pack2(wv.z, wv.z), pack2(wv.w, wv.w) };
#pragma unroll
                    for (int j = 0; j < 4; j++)
#pragma unroll
                        for (int i = 0; i < 4; i++)
                            ffma2(acc[j][i], wj[j], av[i]);
                }
            }
            ab += 14 * 16;
            wp += 4 * 132;
        }
    }

    int n = n0 + img;
#pragma unroll
    for (int j = 0; j < 4; j++) {
        int co = co0 + j;
        float ls = 0.f, lq = 0.f;
        float* dst = g_y2 + (size_t)(n * 128 + co) * 49 + oh * 7;
#pragma unroll
        for (int i = 0; i < 4; i++) {
            float2 f = unpack2(acc[j][i]);
            dst[2 * i] = f.x;
            ls += f.x; lq += f.x * f.x;
            if (i < 3) {               // skip pad (p=7)
                dst[2 * i + 1] = f.y;
                ls += f.y; lq += f.y * f.y;
            }
        }
        atomicAdd(&ssum[co], ls);
        atomicAdd(&ssq[co], lq);
    }
    __syncthreads();
    if (tid < 128) {
        atomicAdd(&g_acc[192 + tid], (double)ssum[tid]);
        atomicAdd(&g_acc[320 + tid], (double)ssq[tid]);
    }
}

// ---------------- bn2+relu + global avg pool + FC ----------------
__global__ void __launch_bounds__(128) k_head(const float* __restrict__ wfc,
                                              const float* __restrict__ bfc,
                                              float* __restrict__ out) {
    __shared__ float sraw[6272];
    __shared__ float pooled[128];
    int tid = threadIdx.x, n = blockIdx.x;
    const float* y2 = g_y2 + (size_t)n * 6272;
    for (int i = tid; i < 6272; i += 128) sraw[i] = y2[i];
    __syncthreads();
    {
        int c = tid;
        float sc = g_scale[96 + c], sh = g_shift[96 + c];
        float s = 0.f;
        const float* p = &sraw[c * 49];
#pragma unroll
        for (int i = 0; i < 49; i++) s += fmaxf(fmaf(p[i], sc, sh), 0.f);
        pooled[c] = s * (1.f / 49.f);
    }
    __syncthreads();
    if (tid < 10) {
        float o = bfc[tid];
        const float* wr = wfc + tid * 128;
#pragma unroll 8
        for (int c = 0; c < 128; c++) o = fmaf(pooled[c], wr[c], o);
        out[(size_t)n * 10 + tid] = o;
    }
}

// ---------------- launch ----------------
extern "C" void kernel_launch(void* const* d_in, const int* in_sizes, int n_in,
                              void* d_out, int out_size) {
    const float* x   = (const float*)d_in[0];
    const float* w0  = (const float*)d_in[1];
    const float* b0  = (const float*)d_in[2];
    const float* g0  = (const float*)d_in[3];
    const float* be0 = (const float*)d_in[4];
    const float* w1  = (const float*)d_in[5];
    const float* b1  = (const float*)d_in[6];
    const float* g1  = (const float*)d_in[7];
    const float* be1 = (const float*)d_in[8];
    const float* w2  = (const float*)d_in[9];
    const float* b2  = (const float*)d_in[10];
    const float* g2  = (const float*)d_in[11];
    const float* be2 = (const float*)d_in[12];
    const float* wfc = (const float*)d_in[13];
    const float* bfc = (const float*)d_in[14];
    float* out = (float*)d_out;

    cudaFuncSetAttribute(k_conv1, cudaFuncAttributeMaxDynamicSharedMemorySize, 102912);
    cudaFuncSetAttribute(k_conv2, cudaFuncAttributeMaxDynamicSharedMemorySize, 183296);

    k_zero<<<2, 256>>>();
    k_stats0<<<NB, 256>>>(x, w0, b0);
    k_fin<<<1, 128>>>(0, 32, 1.0 / (8192.0 * 784.0), g0, be0, 0);
    k_conv1<<<NB * 2, 256, 102912>>>(x, w0, b0, w1, b1);
    k_fin<<<1, 128>>>(64, 64, 1.0 / (8192.0 * 196.0), g1, be1, 32);
    k_conv2<<<NB / 2, 448, 183296>>>(w2, b2);
    k_fin<<<1, 128>>>(192, 128, 1.0 / (8192.0 * 49.0), g2, be2, 96);
    k_head<<<NB, 128>>>(wfc, bfc, out);
}